// round 14
// baseline (speedup 1.0000x reference)
#include <cuda_runtime.h>
#include <cuda_bf16.h>
#include <cstdint>

// ---------- problem constants (fixed instance) ----------
constexpr int S = 3, G = 8, B = 2048, C = 512, P = 64;
constexpr int N = S * G * B;              // 49152
constexpr int OUT_ELEMS = G * P * C;      // 262144
constexpr int KS = 8;                     // split-K for GEMM2
constexpr int KCHUNK = 768;               // 8*768 == 6144 exactly
constexpr int NS2 = KCHUNK / 16;          // 48 stages of k=16
constexpr int BM = 128;
constexpr int APAD = 24;                  // halves per smem row (48 B)
constexpr int STR2 = 72;                  // halves per smem row (144 B)
constexpr int ABLOCKS = N / BM;           // 384 assign CTAs
constexpr int GBLOCKS = (C / 64) * G * KS;// 512 gemm2 CTAs

// ---------- device scratch (no allocations allowed) ----------
__device__ float g_csq[P];
__device__ float g_ivb[P];
__device__ float g_partial[(size_t)KS * OUT_ELEMS];
__device__ __nv_bfloat16 g_whi[P * C];
__device__ __nv_bfloat16 g_wlo[P * C];
__device__ __nv_bfloat16 g_ahi[(size_t)N * P];
__device__ __nv_bfloat16 g_alo[(size_t)N * P];
__device__ int g_flag[ABLOCKS];

// ---------- small helpers ----------
__device__ __forceinline__ uint32_t smem_u32(const void* p) {
    uint32_t a;
    asm("{ .reg .u64 t; cvta.to.shared.u64 t, %1; cvt.u32.u64 %0, t; }" : "=r"(a) : "l"(p));
    return a;
}
__device__ __forceinline__ void bfsplit2(float f0, float f1, uint32_t& ph, uint32_t& pl) {
    asm("cvt.rn.bf16x2.f32 %0, %1, %2;" : "=r"(ph) : "f"(f1), "f"(f0));
    float h0 = __uint_as_float(ph << 16);
    float h1 = __uint_as_float(ph & 0xFFFF0000u);
    float l0 = f0 - h0, l1 = f1 - h1;
    asm("cvt.rn.bf16x2.f32 %0, %1, %2;" : "=r"(pl) : "f"(l1), "f"(l0));
}
__device__ __forceinline__ void mma16816(float* d, const uint32_t* a, const uint32_t* b) {
    asm volatile(
        "mma.sync.aligned.m16n8k16.row.col.f32.bf16.bf16.f32 "
        "{%0,%1,%2,%3}, {%4,%5,%6,%7}, {%8,%9}, {%0,%1,%2,%3};"
        : "+f"(d[0]), "+f"(d[1]), "+f"(d[2]), "+f"(d[3])
        : "r"(a[0]), "r"(a[1]), "r"(a[2]), "r"(a[3]), "r"(b[0]), "r"(b[1]));
}
__device__ __forceinline__ void ldmx2t(uint32_t& r0, uint32_t& r1, uint32_t addr) {
    asm volatile("ldmatrix.sync.aligned.m8n8.x2.trans.shared.b16 {%0,%1}, [%2];"
                 : "=r"(r0), "=r"(r1) : "r"(addr));
}
__device__ __forceinline__ void ldmx4(uint32_t* r, uint32_t addr) {
    asm volatile("ldmatrix.sync.aligned.m8n8.x4.shared.b16 {%0,%1,%2,%3}, [%4];"
                 : "=r"(r[0]), "=r"(r[1]), "=r"(r[2]), "=r"(r[3]) : "r"(addr));
}
__device__ __forceinline__ void ldmx4t(uint32_t* r, uint32_t addr) {
    asm volatile("ldmatrix.sync.aligned.m8n8.x4.trans.shared.b16 {%0,%1,%2,%3}, [%4];"
                 : "=r"(r[0]), "=r"(r[1]), "=r"(r[2]), "=r"(r[3]) : "r"(addr));
}

// ---------- prep: |c|^2, 1/beta, W split, flag reset ----------
__global__ void prep_kernel(const float* __restrict__ W, const float* __restrict__ sf) {
    const int t = threadIdx.x;       // 256
    g_flag[t] = 0;
    if (t < ABLOCKS - 256) g_flag[t + 256] = 0;
    const int p = t >> 2;
    const int q = t & 3;
    const float* wr = W + (size_t)p * C + q * 128;
    uint32_t* whi = reinterpret_cast<uint32_t*>(g_whi + (size_t)p * C + q * 128);
    uint32_t* wlo = reinterpret_cast<uint32_t*>(g_wlo + (size_t)p * C + q * 128);
    float s = 0.f;
#pragma unroll 8
    for (int k = 0; k < 128; k += 2) {
        float f0 = wr[k], f1 = wr[k + 1];
        s += f0 * f0 + f1 * f1;
        uint32_t h, l;
        bfsplit2(f0, f1, h, l);
        whi[k >> 1] = h;
        wlo[k >> 1] = l;
    }
    s += __shfl_xor_sync(0xffffffffu, s, 1);
    s += __shfl_xor_sync(0xffffffffu, s, 2);
    if (q == 0) {
        g_csq[p] = s;
        g_ivb[p] = 1.0f + __expf(-sf[p]);   // 1/sigmoid(sf)
    }
}

// ---------- fused: assign (bids 0..383) + gemm2 (bids 384..895) ----------
__global__ __launch_bounds__(128) void fused_kernel(
    const float* __restrict__ X, float* __restrict__ assign_out)
{
    __shared__ __align__(16) unsigned char SM[37888];

    const int t = threadIdx.x;
    const int w = t >> 5;
    const int lane = t & 31;
    const int g8 = lane >> 2;
    const int t4 = lane & 3;

    if (blockIdx.x < ABLOCKS) {
        // ================= assign body (R12, unchanged math) =================
        auto AsH = reinterpret_cast<__nv_bfloat16(*)[BM][APAD]>(SM);            // [2][128][24]
        auto AsL = reinterpret_cast<__nv_bfloat16(*)[BM][APAD]>(SM + 12288);
        auto WsH = reinterpret_cast<__nv_bfloat16(*)[P][APAD]>(SM + 24576);     // [2][64][24]
        auto WsL = reinterpret_cast<__nv_bfloat16(*)[P][APAD]>(SM + 30720);
        float* Xsq = reinterpret_cast<float*>(SM + 36864);
        float* Csq = reinterpret_cast<float*>(SM + 37376);
        float* Ivb = reinterpret_cast<float*>(SM + 37632);

        const int row_base = blockIdx.x * BM;
        if (t < P) { Csq[t] = g_csq[t]; Ivb[t] = g_ivb[t]; }

        const int xr = t >> 2;
        const int xq = t & 3;
        const bool wlo_role = t >= 64;
        const int u = t & 63;
        const int wr0 = u >> 1;
        const int wc = u & 1;
        const __nv_bfloat16* wsrc = wlo_role ? g_wlo : g_whi;

        const uint32_t aHb = smem_u32(AsH), aLb = smem_u32(AsL);
        const uint32_t wHb = smem_u32(WsH), wLb = smem_u32(WsL);
        const uint32_t aoff = (uint32_t)(w * 32 + (lane & 7) + ((lane >> 3) & 1) * 8) * 48
                            + ((lane >> 4) & 1) * 16;
        const uint32_t boff = (uint32_t)((lane & 7) + ((lane >> 4) & 1) * 8) * 48
                            + ((lane >> 3) & 1) * 16;

        float acc[2][8][4];
#pragma unroll
        for (int mi = 0; mi < 2; mi++)
#pragma unroll
            for (int ni = 0; ni < 8; ni++)
#pragma unroll
                for (int q = 0; q < 4; q++) acc[mi][ni][q] = 0.f;

        float xp[4] = {0.f, 0.f, 0.f, 0.f};
        float4 xv[4];
        uint4 wv0, wv1;

        auto gl_load = [&](int s) {
            const int k0 = s * 16;
#pragma unroll
            for (int i = 0; i < 4; i++)
                xv[i] = *reinterpret_cast<const float4*>(
                    X + (size_t)(row_base + xr + 32 * i) * C + k0 + xq * 4);
            wv0 = *reinterpret_cast<const uint4*>(wsrc + (size_t)wr0 * C + k0 + wc * 8);
            wv1 = *reinterpret_cast<const uint4*>(wsrc + (size_t)(wr0 + 32) * C + k0 + wc * 8);
        };
        auto st_stage = [&](int b) {
#pragma unroll
            for (int i = 0; i < 4; i++) {
                uint32_t h0, l0, h1, l1;
                bfsplit2(xv[i].x, xv[i].y, h0, l0);
                bfsplit2(xv[i].z, xv[i].w, h1, l1);
                xp[i] += xv[i].x * xv[i].x + xv[i].y * xv[i].y +
                         xv[i].z * xv[i].z + xv[i].w * xv[i].w;
                *reinterpret_cast<uint2*>(&AsH[b][xr + 32 * i][xq * 4]) = make_uint2(h0, h1);
                *reinterpret_cast<uint2*>(&AsL[b][xr + 32 * i][xq * 4]) = make_uint2(l0, l1);
            }
            if (!wlo_role) {
                *reinterpret_cast<uint4*>(&WsH[b][wr0][wc * 8]) = wv0;
                *reinterpret_cast<uint4*>(&WsH[b][wr0 + 32][wc * 8]) = wv1;
            } else {
                *reinterpret_cast<uint4*>(&WsL[b][wr0][wc * 8]) = wv0;
                *reinterpret_cast<uint4*>(&WsL[b][wr0 + 32][wc * 8]) = wv1;
            }
        };

        gl_load(0);
        st_stage(0);
        gl_load(1);
        __syncthreads();

#pragma unroll 1
        for (int s = 0; s < 32; s++) {
            const int b = s & 1;
            if (s + 1 < 32) st_stage(b ^ 1);
            if (s + 2 < 32) gl_load(s + 2);

            uint32_t bh[8][2], bl[8][2];
#pragma unroll
            for (int np = 0; np < 4; np++) {
                uint32_t r[4];
                ldmx4(r, wHb + (uint32_t)b * 3072 + boff + np * 768);
                bh[2 * np][0] = r[0]; bh[2 * np][1] = r[1];
                bh[2 * np + 1][0] = r[2]; bh[2 * np + 1][1] = r[3];
                ldmx4(r, wLb + (uint32_t)b * 3072 + boff + np * 768);
                bl[2 * np][0] = r[0]; bl[2 * np][1] = r[1];
                bl[2 * np + 1][0] = r[2]; bl[2 * np + 1][1] = r[3];
            }
#pragma unroll
            for (int mi = 0; mi < 2; mi++) {
                uint32_t ah[4], al_[4];
                ldmx4(ah, aHb + (uint32_t)b * 6144 + aoff + mi * 768);
                ldmx4(al_, aLb + (uint32_t)b * 6144 + aoff + mi * 768);
#pragma unroll
                for (int ni = 0; ni < 8; ni++) {
                    mma16816(acc[mi][ni], ah, bh[ni]);
                    mma16816(acc[mi][ni], ah, bl[ni]);
                    mma16816(acc[mi][ni], al_, bh[ni]);
                }
            }
            __syncthreads();
        }

#pragma unroll
        for (int i = 0; i < 4; i++) {
            float sx = xp[i];
            sx += __shfl_xor_sync(0xffffffffu, sx, 1);
            sx += __shfl_xor_sync(0xffffffffu, sx, 2);
            if (xq == 0) Xsq[xr + 32 * i] = sx;
        }
        __syncthreads();

        float csq_c[16], ivb_c[16];
#pragma unroll
        for (int ni = 0; ni < 8; ni++)
#pragma unroll
            for (int j = 0; j < 2; j++) {
                const int c = ni * 8 + t4 * 2 + j;
                csq_c[2 * ni + j] = Csq[c];
                ivb_c[2 * ni + j] = Ivb[c];
            }

#pragma unroll
        for (int mi = 0; mi < 2; mi++) {
#pragma unroll
            for (int half = 0; half < 2; half++) {
                const int rl = w * 32 + mi * 16 + half * 8 + g8;
                const float xs = Xsq[rl];
                float v[16];
#pragma unroll
                for (int ni = 0; ni < 8; ni++)
#pragma unroll
                    for (int j = 0; j < 2; j++)
                        v[2 * ni + j] = fminf(2.f * acc[mi][ni][2 * half + j] - xs - csq_c[2 * ni + j], 0.f)
                                        * ivb_c[2 * ni + j];
                float m = v[0];
#pragma unroll
                for (int q = 1; q < 16; q++) m = fmaxf(m, v[q]);
                m = fmaxf(m, __shfl_xor_sync(0xffffffffu, m, 1));
                m = fmaxf(m, __shfl_xor_sync(0xffffffffu, m, 2));
                float sum = 0.f;
#pragma unroll
                for (int q = 0; q < 16; q++) { float ex = __expf(v[q] - m); v[q] = ex; sum += ex; }
                sum += __shfl_xor_sync(0xffffffffu, sum, 1);
                sum += __shfl_xor_sync(0xffffffffu, sum, 2);
                const float inv = 1.f / sum;
                const size_t arow = (size_t)(row_base + rl);
                float* orow = assign_out + arow * P + t4 * 2;
                uint32_t* ahp = reinterpret_cast<uint32_t*>(g_ahi) + arow * 32 + t4;
                uint32_t* alp = reinterpret_cast<uint32_t*>(g_alo) + arow * 32 + t4;
#pragma unroll
                for (int ni = 0; ni < 8; ni++) {
                    const float a0 = v[2 * ni] * inv, a1 = v[2 * ni + 1] * inv;
                    *reinterpret_cast<float2*>(orow + ni * 8) = make_float2(a0, a1);
                    uint32_t hh, ll;
                    bfsplit2(a0, a1, hh, ll);
                    ahp[ni * 4] = hh;
                    alp[ni * 4] = ll;
                }
            }
        }

        // publish this block's g_ahi/g_alo rows
        __syncthreads();
        if (t == 0) {
            __threadfence();
            asm volatile("st.release.gpu.b32 [%0], %1;"
                         :: "l"(g_flag + blockIdx.x), "r"(1) : "memory");
        }
    } else {
        // ================= gemm2 body (R12, unchanged math) =================
        const int id = blockIdx.x - ABLOCKS;         // ks-major ordering
        const int ct = id & 7;
        const int gg = (id >> 3) & 7;
        const int ks = id >> 6;
        const int cbase = ct * 64;
        const int jbase0 = ks * KCHUNK;

        // wait for the 6 assign blocks this slice depends on
        if (t == 0) {
#pragma unroll
            for (int i = 0; i < 6; i++) {
                const int j = jbase0 + i * 128;
                const int blk = (((j >> 11) << 14) + (gg << 11) + (j & 2047)) >> 7;
                int v;
                do {
                    asm volatile("ld.acquire.gpu.b32 %0, [%1];"
                                 : "=r"(v) : "l"(g_flag + blk) : "memory");
                    if (!v) __nanosleep(200);
                } while (!v);
            }
        }
        __syncthreads();

        auto AsH = reinterpret_cast<__nv_bfloat16(*)[16][STR2]>(SM);            // [2][16][72]
        auto AsL = reinterpret_cast<__nv_bfloat16(*)[16][STR2]>(SM + 4608);
        auto BsH = reinterpret_cast<__nv_bfloat16(*)[16][STR2]>(SM + 9216);
        auto BsL = reinterpret_cast<__nv_bfloat16(*)[16][STR2]>(SM + 13824);

        const int krow = t >> 3;
        const int chunk = t & 7;

        const uint32_t aH = smem_u32(AsH), aL = smem_u32(AsL);
        const uint32_t bH = smem_u32(BsH), bL = smem_u32(BsL);
        const uint32_t aoffT = (uint32_t)((lane & 7) + ((lane >> 4) & 1) * 8) * (STR2 * 2)
                             + ((lane >> 3) & 1) * 16;
        const int lrow = lane & 15;
        const int tid4 = t4;

        float acc[4][2][4];
#pragma unroll
        for (int mi = 0; mi < 4; mi++)
#pragma unroll
            for (int ni = 0; ni < 2; ni++)
#pragma unroll
                for (int q = 0; q < 4; q++) acc[mi][ni][q] = 0.f;

        uint4 av0, av1;
        float4 xv0, xv1;

        auto row_of = [&](int s) -> size_t {
            const int j = jbase0 + s * 16 + krow;
            return (size_t)(j >> 11) * (G * B) + (size_t)gg * B + (j & 2047);
        };
        auto gl_load = [&](int s) {
            const size_t row = row_of(s);
            av0 = *reinterpret_cast<const uint4*>(g_ahi + row * P + chunk * 8);
            av1 = *reinterpret_cast<const uint4*>(g_alo + row * P + chunk * 8);
            const float* xp = X + row * C + cbase + chunk * 8;
            xv0 = *reinterpret_cast<const float4*>(xp);
            xv1 = *reinterpret_cast<const float4*>(xp + 4);
        };
        auto st_stage = [&](int b) {
            *reinterpret_cast<uint4*>(&AsH[b][krow][chunk * 8]) = av0;
            *reinterpret_cast<uint4*>(&AsL[b][krow][chunk * 8]) = av1;
            uint32_t h[4], l[4];
            bfsplit2(xv0.x, xv0.y, h[0], l[0]);
            bfsplit2(xv0.z, xv0.w, h[1], l[1]);
            bfsplit2(xv1.x, xv1.y, h[2], l[2]);
            bfsplit2(xv1.z, xv1.w, h[3], l[3]);
            *reinterpret_cast<uint4*>(&BsH[b][krow][chunk * 8]) = make_uint4(h[0], h[1], h[2], h[3]);
            *reinterpret_cast<uint4*>(&BsL[b][krow][chunk * 8]) = make_uint4(l[0], l[1], l[2], l[3]);
        };

        gl_load(0);
        st_stage(0);
        gl_load(1);
        __syncthreads();

#pragma unroll 1
        for (int s = 0; s < NS2; s++) {
            const int b = s & 1;
            if (s + 1 < NS2) st_stage(b ^ 1);
            if (s + 2 < NS2) gl_load(s + 2);

            uint32_t bh[2][2], bl[2][2];
#pragma unroll
            for (int ni = 0; ni < 2; ni++) {
                const uint32_t off =
                    (uint32_t)((b * 16 + lrow) * STR2 + (w * 16 + ni * 8)) * 2;
                ldmx2t(bh[ni][0], bh[ni][1], bH + off);
                ldmx2t(bl[ni][0], bl[ni][1], bL + off);
            }
#pragma unroll
            for (int mi = 0; mi < 4; mi++) {
                uint32_t ah[4], al_[4];
                const uint32_t ao = (uint32_t)b * (16 * STR2 * 2) + aoffT + mi * 32;
                ldmx4t(ah, aH + ao);
                ldmx4t(al_, aL + ao);
#pragma unroll
                for (int ni = 0; ni < 2; ni++) {
                    mma16816(acc[mi][ni], ah, bh[ni]);
                    mma16816(acc[mi][ni], ah, bl[ni]);
                    mma16816(acc[mi][ni], al_, bh[ni]);
                }
            }
            __syncthreads();
        }

        float* dst = g_partial + ((size_t)ks * G + gg) * (size_t)(P * C);
#pragma unroll
        for (int mi = 0; mi < 4; mi++) {
            const int p0_ = mi * 16 + g8;
#pragma unroll
            for (int ni = 0; ni < 2; ni++) {
                const int cc = cbase + w * 16 + ni * 8 + tid4 * 2;
                *reinterpret_cast<float2*>(dst + (size_t)p0_ * C + cc) =
                    make_float2(acc[mi][ni][0], acc[mi][ni][1]);
                *reinterpret_cast<float2*>(dst + (size_t)(p0_ + 8) * C + cc) =
                    make_float2(acc[mi][ni][2], acc[mi][ni][3]);
            }
        }
    }
}

// ---------- deterministic split-K reduction (vectorized) ----------
__global__ void reduce_kernel(float* __restrict__ out) {
    const int i = blockIdx.x * blockDim.x + threadIdx.x;
    if (i < OUT_ELEMS / 4) {
        const float4* src = reinterpret_cast<const float4*>(g_partial);
        float4 s = src[i];
#pragma unroll
        for (int ks = 1; ks < KS; ks++) {
            float4 v = src[(size_t)ks * (OUT_ELEMS / 4) + i];
            s.x += v.x; s.y += v.y; s.z += v.z; s.w += v.w;
        }
        reinterpret_cast<float4*>(out)[i] = s;
    }
}

// ---------- launch ----------
extern "C" void kernel_launch(void* const* d_in, const int* in_sizes, int n_in,
                              void* d_out, int out_size) {
    const float* X  = (const float*)d_in[0];   // node_feats [S, G*B, C]
    const float* W  = (const float*)d_in[1];   // weight [P, C]
    const float* sf = (const float*)d_in[2];   // smooth_factor [P]
    float* out = (float*)d_out;                // [outputs (G,P,C) | assign (N,P)]
    float* assign_out = out + OUT_ELEMS;

    prep_kernel<<<1, 256>>>(W, sf);
    fused_kernel<<<ABLOCKS + GBLOCKS, 128>>>(X, assign_out);
    reduce_kernel<<<(OUT_ELEMS / 4 + 255) / 256, 256>>>(out);
}

// round 15
// speedup vs baseline: 1.5539x; 1.5539x over previous
#include <cuda_runtime.h>
#include <cuda_bf16.h>
#include <cstdint>

// ---------- problem constants (fixed instance) ----------
constexpr int S = 3, G = 8, B = 2048, C = 512, P = 64;
constexpr int N = S * G * B;              // 49152
constexpr int OUT_ELEMS = G * P * C;      // 262144
constexpr int KS = 8;                     // split-K for GEMM2
constexpr int KCHUNK = 768;               // 8*768 == 6144 exactly
constexpr int NS2 = KCHUNK / 16;          // 48 stages of k=16

// ---------- device scratch (no allocations allowed) ----------
__device__ float g_csq[P];
__device__ float g_ivb[P];
__device__ float g_partial[(size_t)KS * OUT_ELEMS];
__device__ __nv_bfloat16 g_whi[P * C];
__device__ __nv_bfloat16 g_wlo[P * C];
__device__ __nv_bfloat16 g_ahi[(size_t)N * P];
__device__ __nv_bfloat16 g_alo[(size_t)N * P];

// ---------- small helpers ----------
__device__ __forceinline__ uint32_t smem_u32(const void* p) {
    uint32_t a;
    asm("{ .reg .u64 t; cvta.to.shared.u64 t, %1; cvt.u32.u64 %0, t; }" : "=r"(a) : "l"(p));
    return a;
}
__device__ __forceinline__ void bfsplit2(float f0, float f1, uint32_t& ph, uint32_t& pl) {
    asm("cvt.rn.bf16x2.f32 %0, %1, %2;" : "=r"(ph) : "f"(f1), "f"(f0));
    float h0 = __uint_as_float(ph << 16);
    float h1 = __uint_as_float(ph & 0xFFFF0000u);
    float l0 = f0 - h0, l1 = f1 - h1;
    asm("cvt.rn.bf16x2.f32 %0, %1, %2;" : "=r"(pl) : "f"(l1), "f"(l0));
}
__device__ __forceinline__ void mma16816(float* d, const uint32_t* a, const uint32_t* b) {
    asm volatile(
        "mma.sync.aligned.m16n8k16.row.col.f32.bf16.bf16.f32 "
        "{%0,%1,%2,%3}, {%4,%5,%6,%7}, {%8,%9}, {%0,%1,%2,%3};"
        : "+f"(d[0]), "+f"(d[1]), "+f"(d[2]), "+f"(d[3])
        : "r"(a[0]), "r"(a[1]), "r"(a[2]), "r"(a[3]), "r"(b[0]), "r"(b[1]));
}
__device__ __forceinline__ void ldmx2t(uint32_t& r0, uint32_t& r1, uint32_t addr) {
    asm volatile("ldmatrix.sync.aligned.m8n8.x2.trans.shared.b16 {%0,%1}, [%2];"
                 : "=r"(r0), "=r"(r1) : "r"(addr));
}
__device__ __forceinline__ void ldmx4(uint32_t* r, uint32_t addr) {
    asm volatile("ldmatrix.sync.aligned.m8n8.x4.shared.b16 {%0,%1,%2,%3}, [%4];"
                 : "=r"(r[0]), "=r"(r[1]), "=r"(r[2]), "=r"(r[3]) : "r"(addr));
}
__device__ __forceinline__ void ldmx4t(uint32_t* r, uint32_t addr) {
    asm volatile("ldmatrix.sync.aligned.m8n8.x4.trans.shared.b16 {%0,%1,%2,%3}, [%4];"
                 : "=r"(r[0]), "=r"(r[1]), "=r"(r[2]), "=r"(r[3]) : "r"(addr));
}

// ---------- prep v2: one CTA per centroid row (grid=64, 128 thr) ----------
__global__ void prep_kernel(const float* __restrict__ W, const float* __restrict__ sf) {
    __shared__ float warp_s[4];
    const int p = blockIdx.x;
    const int t = threadIdx.x;           // 128: one float4 per thread
    const float4 v = *reinterpret_cast<const float4*>(W + (size_t)p * C + t * 4);
    uint32_t h0, l0, h1, l1;
    bfsplit2(v.x, v.y, h0, l0);
    bfsplit2(v.z, v.w, h1, l1);
    *reinterpret_cast<uint2*>(g_whi + (size_t)p * C + t * 4) = make_uint2(h0, h1);
    *reinterpret_cast<uint2*>(g_wlo + (size_t)p * C + t * 4) = make_uint2(l0, l1);
    float s = v.x * v.x + v.y * v.y + v.z * v.z + v.w * v.w;
#pragma unroll
    for (int d = 1; d < 32; d <<= 1) s += __shfl_xor_sync(0xffffffffu, s, d);
    if ((t & 31) == 0) warp_s[t >> 5] = s;
    __syncthreads();
    if (t == 0) {
        g_csq[p] = warp_s[0] + warp_s[1] + warp_s[2] + warp_s[3];
        g_ivb[p] = 1.0f + __expf(-sf[p]);   // 1/sigmoid(sf)
    }
}

// ---------- fused GEMM1 (HMMA split x3) + softmax -> assign (R12) ----------
constexpr int BM = 128;
constexpr int APAD = 24;   // halves per smem row (48 B)

__global__ __launch_bounds__(128) void assign_tc(
    const float* __restrict__ X, float* __restrict__ assign_out)
{
    __shared__ __align__(16) __nv_bfloat16 AsH[2][BM][APAD];
    __shared__ __align__(16) __nv_bfloat16 AsL[2][BM][APAD];
    __shared__ __align__(16) __nv_bfloat16 WsH[2][P][APAD];
    __shared__ __align__(16) __nv_bfloat16 WsL[2][P][APAD];
    __shared__ float Xsq[BM];
    __shared__ float Csq[P];
    __shared__ float Ivb[P];

    const int t = threadIdx.x;
    const int w = t >> 5;
    const int lane = t & 31;
    const int g8 = lane >> 2;
    const int t4 = lane & 3;
    const int row_base = blockIdx.x * BM;

    if (t < P) { Csq[t] = g_csq[t]; Ivb[t] = g_ivb[t]; }

    const int xr = t >> 2;
    const int xq = t & 3;
    const bool wlo_role = t >= 64;
    const int u = t & 63;
    const int wr0 = u >> 1;
    const int wc = u & 1;
    const __nv_bfloat16* wsrc = wlo_role ? g_wlo : g_whi;

    const uint32_t aHb = smem_u32(AsH), aLb = smem_u32(AsL);
    const uint32_t wHb = smem_u32(WsH), wLb = smem_u32(WsL);
    const uint32_t aoff = (uint32_t)(w * 32 + (lane & 7) + ((lane >> 3) & 1) * 8) * 48
                        + ((lane >> 4) & 1) * 16;
    const uint32_t boff = (uint32_t)((lane & 7) + ((lane >> 4) & 1) * 8) * 48
                        + ((lane >> 3) & 1) * 16;

    float acc[2][8][4];
#pragma unroll
    for (int mi = 0; mi < 2; mi++)
#pragma unroll
        for (int ni = 0; ni < 8; ni++)
#pragma unroll
            for (int q = 0; q < 4; q++) acc[mi][ni][q] = 0.f;

    float xp[4] = {0.f, 0.f, 0.f, 0.f};
    float4 xv[4];
    uint4 wv0, wv1;

    auto gl_load = [&](int s) {
        const int k0 = s * 16;
#pragma unroll
        for (int i = 0; i < 4; i++)
            xv[i] = *reinterpret_cast<const float4*>(
                X + (size_t)(row_base + xr + 32 * i) * C + k0 + xq * 4);
        wv0 = *reinterpret_cast<const uint4*>(wsrc + (size_t)wr0 * C + k0 + wc * 8);
        wv1 = *reinterpret_cast<const uint4*>(wsrc + (size_t)(wr0 + 32) * C + k0 + wc * 8);
    };
    auto st_stage = [&](int b) {
#pragma unroll
        for (int i = 0; i < 4; i++) {
            uint32_t h0, l0, h1, l1;
            bfsplit2(xv[i].x, xv[i].y, h0, l0);
            bfsplit2(xv[i].z, xv[i].w, h1, l1);
            xp[i] += xv[i].x * xv[i].x + xv[i].y * xv[i].y +
                     xv[i].z * xv[i].z + xv[i].w * xv[i].w;
            *reinterpret_cast<uint2*>(&AsH[b][xr + 32 * i][xq * 4]) = make_uint2(h0, h1);
            *reinterpret_cast<uint2*>(&AsL[b][xr + 32 * i][xq * 4]) = make_uint2(l0, l1);
        }
        if (!wlo_role) {
            *reinterpret_cast<uint4*>(&WsH[b][wr0][wc * 8]) = wv0;
            *reinterpret_cast<uint4*>(&WsH[b][wr0 + 32][wc * 8]) = wv1;
        } else {
            *reinterpret_cast<uint4*>(&WsL[b][wr0][wc * 8]) = wv0;
            *reinterpret_cast<uint4*>(&WsL[b][wr0 + 32][wc * 8]) = wv1;
        }
    };

    gl_load(0);
    st_stage(0);
    gl_load(1);
    __syncthreads();

#pragma unroll 1
    for (int s = 0; s < 32; s++) {
        const int b = s & 1;
        if (s + 1 < 32) st_stage(b ^ 1);
        if (s + 2 < 32) gl_load(s + 2);

        uint32_t bh[8][2], bl[8][2];
#pragma unroll
        for (int np = 0; np < 4; np++) {
            uint32_t r[4];
            ldmx4(r, wHb + (uint32_t)b * 3072 + boff + np * 768);
            bh[2 * np][0] = r[0]; bh[2 * np][1] = r[1];
            bh[2 * np + 1][0] = r[2]; bh[2 * np + 1][1] = r[3];
            ldmx4(r, wLb + (uint32_t)b * 3072 + boff + np * 768);
            bl[2 * np][0] = r[0]; bl[2 * np][1] = r[1];
            bl[2 * np + 1][0] = r[2]; bl[2 * np + 1][1] = r[3];
        }
#pragma unroll
        for (int mi = 0; mi < 2; mi++) {
            uint32_t ah[4], al_[4];
            ldmx4(ah, aHb + (uint32_t)b * 6144 + aoff + mi * 768);
            ldmx4(al_, aLb + (uint32_t)b * 6144 + aoff + mi * 768);
#pragma unroll
            for (int ni = 0; ni < 8; ni++) {
                mma16816(acc[mi][ni], ah, bh[ni]);
                mma16816(acc[mi][ni], ah, bl[ni]);
                mma16816(acc[mi][ni], al_, bh[ni]);
            }
        }

        __syncthreads();
    }

#pragma unroll
    for (int i = 0; i < 4; i++) {
        float sx = xp[i];
        sx += __shfl_xor_sync(0xffffffffu, sx, 1);
        sx += __shfl_xor_sync(0xffffffffu, sx, 2);
        if (xq == 0) Xsq[xr + 32 * i] = sx;
    }
    __syncthreads();

    float csq_c[16], ivb_c[16];
#pragma unroll
    for (int ni = 0; ni < 8; ni++)
#pragma unroll
        for (int j = 0; j < 2; j++) {
            const int c = ni * 8 + t4 * 2 + j;
            csq_c[2 * ni + j] = Csq[c];
            ivb_c[2 * ni + j] = Ivb[c];
        }

#pragma unroll
    for (int mi = 0; mi < 2; mi++) {
#pragma unroll
        for (int half = 0; half < 2; half++) {
            const int rl = w * 32 + mi * 16 + half * 8 + g8;
            const float xs = Xsq[rl];
            float v[16];
#pragma unroll
            for (int ni = 0; ni < 8; ni++)
#pragma unroll
                for (int j = 0; j < 2; j++)
                    v[2 * ni + j] = fminf(2.f * acc[mi][ni][2 * half + j] - xs - csq_c[2 * ni + j], 0.f)
                                    * ivb_c[2 * ni + j];
            float m = v[0];
#pragma unroll
            for (int q = 1; q < 16; q++) m = fmaxf(m, v[q]);
            m = fmaxf(m, __shfl_xor_sync(0xffffffffu, m, 1));
            m = fmaxf(m, __shfl_xor_sync(0xffffffffu, m, 2));
            float sum = 0.f;
#pragma unroll
            for (int q = 0; q < 16; q++) { float ex = __expf(v[q] - m); v[q] = ex; sum += ex; }
            sum += __shfl_xor_sync(0xffffffffu, sum, 1);
            sum += __shfl_xor_sync(0xffffffffu, sum, 2);
            const float inv = 1.f / sum;
            const size_t arow = (size_t)(row_base + rl);
            float* orow = assign_out + arow * P + t4 * 2;
            uint32_t* ahp = reinterpret_cast<uint32_t*>(g_ahi) + arow * 32 + t4;
            uint32_t* alp = reinterpret_cast<uint32_t*>(g_alo) + arow * 32 + t4;
#pragma unroll
            for (int ni = 0; ni < 8; ni++) {
                const float a0 = v[2 * ni] * inv, a1 = v[2 * ni + 1] * inv;
                *reinterpret_cast<float2*>(orow + ni * 8) = make_float2(a0, a1);
                uint32_t hh, ll;
                bfsplit2(a0, a1, hh, ll);
                ahp[ni * 4] = hh;
                alp[ni * 4] = ll;
            }
        }
    }
}

// ---------- GEMM2 on HMMA (R12) ----------
constexpr int STR2 = 72;   // halves per smem row (144 B)

__global__ __launch_bounds__(128) void gemm2_mma(const float* __restrict__ X)
{
    __shared__ __align__(16) __nv_bfloat16 AsH[2][16][STR2];
    __shared__ __align__(16) __nv_bfloat16 AsL[2][16][STR2];
    __shared__ __align__(16) __nv_bfloat16 BsH[2][16][STR2];
    __shared__ __align__(16) __nv_bfloat16 BsL[2][16][STR2];

    const int t = threadIdx.x;
    const int w = t >> 5;
    const int lane = t & 31;
    const int g8 = lane >> 2;
    const int tid4 = lane & 3;

    const int ct = blockIdx.x;
    const int gg = blockIdx.y;
    const int ks = blockIdx.z;
    const int cbase = ct * 64;
    const int jbase0 = ks * KCHUNK;

    const int krow = t >> 3;
    const int chunk = t & 7;

    const uint32_t aH = smem_u32(AsH), aL = smem_u32(AsL);
    const uint32_t bH = smem_u32(BsH), bL = smem_u32(BsL);
    const uint32_t aoffT = (uint32_t)((lane & 7) + ((lane >> 4) & 1) * 8) * (STR2 * 2)
                         + ((lane >> 3) & 1) * 16;
    const int lrow = lane & 15;

    float acc[4][2][4];
#pragma unroll
    for (int mi = 0; mi < 4; mi++)
#pragma unroll
        for (int ni = 0; ni < 2; ni++)
#pragma unroll
            for (int q = 0; q < 4; q++) acc[mi][ni][q] = 0.f;

    uint4 av0, av1;
    float4 xv0, xv1;

    auto row_of = [&](int s) -> size_t {
        const int j = jbase0 + s * 16 + krow;
        return (size_t)(j >> 11) * (G * B) + (size_t)gg * B + (j & 2047);
    };
    auto gl_load = [&](int s) {
        const size_t row = row_of(s);
        av0 = *reinterpret_cast<const uint4*>(g_ahi + row * P + chunk * 8);
        av1 = *reinterpret_cast<const uint4*>(g_alo + row * P + chunk * 8);
        const float* xp = X + row * C + cbase + chunk * 8;
        xv0 = *reinterpret_cast<const float4*>(xp);
        xv1 = *reinterpret_cast<const float4*>(xp + 4);
    };
    auto st_stage = [&](int b) {
        *reinterpret_cast<uint4*>(&AsH[b][krow][chunk * 8]) = av0;
        *reinterpret_cast<uint4*>(&AsL[b][krow][chunk * 8]) = av1;
        uint32_t h[4], l[4];
        bfsplit2(xv0.x, xv0.y, h[0], l[0]);
        bfsplit2(xv0.z, xv0.w, h[1], l[1]);
        bfsplit2(xv1.x, xv1.y, h[2], l[2]);
        bfsplit2(xv1.z, xv1.w, h[3], l[3]);
        *reinterpret_cast<uint4*>(&BsH[b][krow][chunk * 8]) = make_uint4(h[0], h[1], h[2], h[3]);
        *reinterpret_cast<uint4*>(&BsL[b][krow][chunk * 8]) = make_uint4(l[0], l[1], l[2], l[3]);
    };

    gl_load(0);
    st_stage(0);
    gl_load(1);
    __syncthreads();

#pragma unroll 1
    for (int s = 0; s < NS2; s++) {
        const int b = s & 1;
        if (s + 1 < NS2) st_stage(b ^ 1);
        if (s + 2 < NS2) gl_load(s + 2);

        uint32_t bh[2][2], bl[2][2];
#pragma unroll
        for (int ni = 0; ni < 2; ni++) {
            const uint32_t off =
                (uint32_t)((b * 16 + lrow) * STR2 + (w * 16 + ni * 8)) * 2;
            ldmx2t(bh[ni][0], bh[ni][1], bH + off);
            ldmx2t(bl[ni][0], bl[ni][1], bL + off);
        }
#pragma unroll
        for (int mi = 0; mi < 4; mi++) {
            uint32_t ah[4], al_[4];
            const uint32_t ao = (uint32_t)b * (16 * STR2 * 2) + aoffT + mi * 32;
            ldmx4t(ah, aH + ao);
            ldmx4t(al_, aL + ao);
#pragma unroll
            for (int ni = 0; ni < 2; ni++) {
                mma16816(acc[mi][ni], ah, bh[ni]);
                mma16816(acc[mi][ni], ah, bl[ni]);
                mma16816(acc[mi][ni], al_, bh[ni]);
            }
        }

        __syncthreads();
    }

    float* dst = g_partial + ((size_t)ks * G + gg) * (size_t)(P * C);
#pragma unroll
    for (int mi = 0; mi < 4; mi++) {
        const int p0_ = mi * 16 + g8;
#pragma unroll
        for (int ni = 0; ni < 2; ni++) {
            const int cc = cbase + w * 16 + ni * 8 + tid4 * 2;
            *reinterpret_cast<float2*>(dst + (size_t)p0_ * C + cc) =
                make_float2(acc[mi][ni][0], acc[mi][ni][1]);
            *reinterpret_cast<float2*>(dst + (size_t)(p0_ + 8) * C + cc) =
                make_float2(acc[mi][ni][2], acc[mi][ni][3]);
        }
    }
}

// ---------- deterministic split-K reduction (vectorized) ----------
__global__ void reduce_kernel(float* __restrict__ out) {
    const int i = blockIdx.x * blockDim.x + threadIdx.x;
    if (i < OUT_ELEMS / 4) {
        const float4* src = reinterpret_cast<const float4*>(g_partial);
        float4 s = src[i];
#pragma unroll
        for (int ks = 1; ks < KS; ks++) {
            float4 v = src[(size_t)ks * (OUT_ELEMS / 4) + i];
            s.x += v.x; s.y += v.y; s.z += v.z; s.w += v.w;
        }
        reinterpret_cast<float4*>(out)[i] = s;
    }
}

// ---------- launch ----------
extern "C" void kernel_launch(void* const* d_in, const int* in_sizes, int n_in,
                              void* d_out, int out_size) {
    const float* X  = (const float*)d_in[0];   // node_feats [S, G*B, C]
    const float* W  = (const float*)d_in[1];   // weight [P, C]
    const float* sf = (const float*)d_in[2];   // smooth_factor [P]
    float* out = (float*)d_out;                // [outputs (G,P,C) | assign (N,P)]
    float* assign_out = out + OUT_ELEMS;

    prep_kernel<<<P, 128>>>(W, sf);
    assign_tc<<<N / BM, 128>>>(X, assign_out);
    gemm2_mma<<<dim3(C / 64, G, KS), 128>>>(X);
    reduce_kernel<<<(OUT_ELEMS / 4 + 255) / 256, 256>>>(out);
}